// round 8
// baseline (speedup 1.0000x reference)
#include <cuda_runtime.h>
#include <math.h>

#define D_DET   363
#define N_ANG   360
#define IMG     256
#define PAD     76
#define SROW    544                    // padded row length (float2 pairs)
#define NROWS   720                    // B * N_ANG
#define BATCH_OFF (N_ANG * SROW)       // float2 elements between batch 0 and batch 1

// Pair-packed, zero-padded filtered sinogram: g_filt2[row][i] = (f[i], f[i+1])
__device__ float2 g_filt2[NROWS * SROW];

// ============================================================================
// Kernel 1: ramp-filter via exact circular convolution (== ifft(fft*2|f|).real)
// Verbatim the R7-proven kernel; only the final global write is pair-packed.
// ============================================================================
__global__ __launch_bounds__(192) void filter_kernel(const float* __restrict__ sino) {
    __shared__ float s_h2[736];        // s_h2[j+4] = h[(j-362) mod 363], zeros elsewhere
    __shared__ float s_row[2][368];
    __shared__ float s_out[2][546];    // full padded rows (zeros in pads)

    int t = threadIdx.x;               // 0..191
    int r = t / 96;                    // local row
    int j = t - r * 96;
    int row0 = blockIdx.x * 2;

    // ---- build h2 table ----
    // h[n] = (182 cos(362 n pi/363) - 181 cos(364 n pi/363) - 1) / (363^2 sin^2(n pi/363))
    for (int i = t; i < 736; i += 192) {
        float v = 0.0f;
        int jj = i - 4;
        if (jj >= 0 && jj <= 724) {
            int n = (jj >= 362) ? (jj - 362) : (jj + 1);   // (jj-362) mod 363
            if (n == 0) {
                v = 2.0f * 181.0f * 182.0f / (363.0f * 363.0f);
            } else {
                int r1 = (362 * n) % 726;                  // exact mod-2pi reduction
                int r2 = (364 * n) % 726;
                float c1 = cospif((float)r1 * (1.0f / 363.0f));
                float c2 = cospif((float)r2 * (1.0f / 363.0f));
                float s  = sinpif((float)n  * (1.0f / 363.0f));
                v = (182.0f * c1 - 181.0f * c2 - 1.0f) / (363.0f * 363.0f * s * s);
            }
        }
        s_h2[i] = v;
    }
    // ---- load input rows ----
    for (int i = t; i < 2 * 368; i += 192) {
        int rr = i / 368, c = i - rr * 368;
        s_row[rr][c] = (c < D_DET) ? sino[(row0 + rr) * D_DET + c] : 0.0f;
    }
    // ---- zero padded output rows ----
    for (int i = t; i < 2 * 546; i += 192) ((float*)s_out)[i] = 0.0f;
    __syncthreads();

    // ---- convolution: outputs d0..d0+3, h window slides one element per k ----
    if (j < 91) {
        int d0 = 4 * j;                          // 0..360
        const float* sr = s_row[r];
        int base = 366 + d0;                     // = 362 + d0 + 4 (table offset)
        float w0 = s_h2[base + 0];
        float w1 = s_h2[base + 1];
        float w2 = s_h2[base + 2];
        float w3 = s_h2[base + 3];
        float a0 = 0.f, a1 = 0.f, a2 = 0.f, a3 = 0.f;
        #pragma unroll 4
        for (int k = 0; k < D_DET; k++) {
            float sv = sr[k];
            a0 = fmaf(sv, w0, a0);
            a1 = fmaf(sv, w1, a1);
            a2 = fmaf(sv, w2, a2);
            a3 = fmaf(sv, w3, a3);
            w3 = w2; w2 = w1; w1 = w0;
            w0 = s_h2[base - 1 - k];             // min index 3: in-bounds
        }
        s_out[r][PAD + d0 + 0] = a0;
        s_out[r][PAD + d0 + 1] = a1;
        s_out[r][PAD + d0 + 2] = a2;
        if (d0 + 3 < D_DET) s_out[r][PAD + d0 + 3] = a3;
    }
    __syncthreads();

    // ---- write pair-packed padded rows: g_filt2[row][c] = (f[c], f[c+1]) ----
    for (int i = t; i < 2 * SROW; i += 192) {
        int rr = i / SROW, c = i - rr * SROW;   // c in [0,543]; s_out[.][544] is zero
        g_filt2[(row0 + rr) * SROW + c] = make_float2(s_out[rr][c], s_out[rr][c + 1]);
    }
}

// ============================================================================
// Kernel 2: backprojection. 32x8 pixel tile per block (32x4 threads); each
// thread computes 2 y-pixels x 2 batches (4 independent accumulators, MLP=4).
// One LDG.64 per bilinear sample. floorf (proven); u in (0,514), no bounds
// checks thanks to zero padding.
// ============================================================================
__global__ __launch_bounds__(128) void bp_kernel(float* __restrict__ out) {
    __shared__ float2 s_trig[N_ANG];
    int tid = threadIdx.y * 32 + threadIdx.x;

    const float C1 = 32761.0f / (127.5f * 1.41421356237309515f);  // 181^2/(127.5*sqrt2)
    for (int a = tid; a < N_ANG; a += 128) {
        float sa, ca;
        sincospif((float)a * (1.0f / 360.0f), &sa, &ca);          // angle = a*pi/360
        s_trig[a] = make_float2(ca * C1, sa * C1);
    }
    __syncthreads();

    int x  = blockIdx.x * 32 + threadIdx.x;
    int y0 = blockIdx.y * 8 + threadIdx.y;
    int y1 = y0 + 4;
    float xf  = fmaf((float)x,  2.0f / 255.0f, -1.0f);
    float yf0 = fmaf((float)y0, 2.0f / 255.0f, -1.0f);
    float yf1 = fmaf((float)y1, 2.0f / 255.0f, -1.0f);

    float accA0 = 0.f, accA1 = 0.f, accB0 = 0.f, accB1 = 0.f;
    const float2* p = g_filt2;

    #pragma unroll 4
    for (int a = 0; a < N_ANG; a++) {
        float2 cs = s_trig[a];
        float ub = fmaf(xf, cs.x, 257.0f);        // 257 = PAD + (D-1)/2
        float u0 = fmaf(yf0, cs.y, ub);
        float u1 = fmaf(yf1, cs.y, ub);

        float uf0 = floorf(u0);
        float uf1 = floorf(u1);
        int   i0  = (int)uf0;
        int   i1  = (int)uf1;
        float w0  = u0 - uf0;
        float w1  = u1 - uf1;

        float2 vA0 = __ldg(p + i0);
        float2 vB0 = __ldg(p + i0 + BATCH_OFF);
        float2 vA1 = __ldg(p + i1);
        float2 vB1 = __ldg(p + i1 + BATCH_OFF);

        accA0 = fmaf(w0, vA0.y - vA0.x, accA0 + vA0.x);
        accB0 = fmaf(w0, vB0.y - vB0.x, accB0 + vB0.x);
        accA1 = fmaf(w1, vA1.y - vA1.x, accA1 + vA1.x);
        accB1 = fmaf(w1, vB1.y - vB1.x, accB1 + vB1.x);
        p += SROW;
    }

    const float SC = (float)(M_PI / 360.0);
    out[            y0 * IMG + x] = accA0 * SC;
    out[            y1 * IMG + x] = accA1 * SC;
    out[IMG * IMG + y0 * IMG + x] = accB0 * SC;
    out[IMG * IMG + y1 * IMG + x] = accB1 * SC;
}

// ============================================================================
extern "C" void kernel_launch(void* const* d_in, const int* in_sizes, int n_in,
                              void* d_out, int out_size) {
    const float* sino = (const float*)d_in[0];   // (2,1,360,363) float32
    float* out = (float*)d_out;                  // (2,1,256,256) float32

    filter_kernel<<<NROWS / 2, 192>>>(sino);
    bp_kernel<<<dim3(IMG / 32, IMG / 8), dim3(32, 4)>>>(out);
}

// round 9
// speedup vs baseline: 2.1089x; 2.1089x over previous
#include <cuda_runtime.h>
#include <math.h>

#define D_DET   363
#define N_ANG   360
#define HALF_A  180
#define IMG     256
#define PAD     76
#define SROW    544                    // padded row length (float2 pairs)
#define NROWS   720                    // B * N_ANG
#define BATCH_OFF (N_ANG * SROW)       // float2 elements between batch 0 and batch 1

// Pair-packed, zero-padded filtered sinogram: g_filt2[row][i] = (f[i], f[i+1])
__device__ float2 g_filt2[NROWS * SROW];
// Partial backprojection sums: [batch*2 + half][pixel]
__device__ float  g_part[4][IMG * IMG];

// ============================================================================
// Kernel 1: ramp-filter via exact circular convolution (== ifft(fft*2|f|).real)
// Verbatim the R8-proven kernel (passed correctness).
// ============================================================================
__global__ __launch_bounds__(192) void filter_kernel(const float* __restrict__ sino) {
    __shared__ float s_h2[736];        // s_h2[j+4] = h[(j-362) mod 363], zeros elsewhere
    __shared__ float s_row[2][368];
    __shared__ float s_out[2][546];    // full padded rows (zeros in pads)

    int t = threadIdx.x;               // 0..191
    int r = t / 96;                    // local row
    int j = t - r * 96;
    int row0 = blockIdx.x * 2;

    // h[n] = (182 cos(362 n pi/363) - 181 cos(364 n pi/363) - 1) / (363^2 sin^2(n pi/363))
    for (int i = t; i < 736; i += 192) {
        float v = 0.0f;
        int jj = i - 4;
        if (jj >= 0 && jj <= 724) {
            int n = (jj >= 362) ? (jj - 362) : (jj + 1);   // (jj-362) mod 363
            if (n == 0) {
                v = 2.0f * 181.0f * 182.0f / (363.0f * 363.0f);
            } else {
                int r1 = (362 * n) % 726;                  // exact mod-2pi reduction
                int r2 = (364 * n) % 726;
                float c1 = cospif((float)r1 * (1.0f / 363.0f));
                float c2 = cospif((float)r2 * (1.0f / 363.0f));
                float s  = sinpif((float)n  * (1.0f / 363.0f));
                v = (182.0f * c1 - 181.0f * c2 - 1.0f) / (363.0f * 363.0f * s * s);
            }
        }
        s_h2[i] = v;
    }
    for (int i = t; i < 2 * 368; i += 192) {
        int rr = i / 368, c = i - rr * 368;
        s_row[rr][c] = (c < D_DET) ? sino[(row0 + rr) * D_DET + c] : 0.0f;
    }
    for (int i = t; i < 2 * 546; i += 192) ((float*)s_out)[i] = 0.0f;
    __syncthreads();

    if (j < 91) {
        int d0 = 4 * j;                          // 0..360
        const float* sr = s_row[r];
        int base = 366 + d0;                     // = 362 + d0 + 4 (table offset)
        float w0 = s_h2[base + 0];
        float w1 = s_h2[base + 1];
        float w2 = s_h2[base + 2];
        float w3 = s_h2[base + 3];
        float a0 = 0.f, a1 = 0.f, a2 = 0.f, a3 = 0.f;
        #pragma unroll 4
        for (int k = 0; k < D_DET; k++) {
            float sv = sr[k];
            a0 = fmaf(sv, w0, a0);
            a1 = fmaf(sv, w1, a1);
            a2 = fmaf(sv, w2, a2);
            a3 = fmaf(sv, w3, a3);
            w3 = w2; w2 = w1; w1 = w0;
            w0 = s_h2[base - 1 - k];             // min index 3: in-bounds
        }
        s_out[r][PAD + d0 + 0] = a0;
        s_out[r][PAD + d0 + 1] = a1;
        s_out[r][PAD + d0 + 2] = a2;
        if (d0 + 3 < D_DET) s_out[r][PAD + d0 + 3] = a3;
    }
    __syncthreads();

    // pair-packed padded rows: g_filt2[row][c] = (f[c], f[c+1])
    for (int i = t; i < 2 * SROW; i += 192) {
        int rr = i / SROW, c = i - rr * SROW;   // s_out[.][544] is zero
        g_filt2[(row0 + rr) * SROW + c] = make_float2(s_out[rr][c], s_out[rr][c + 1]);
    }
}

// ============================================================================
// Kernel 2: backprojection, R7-proven per-thread structure. 16x16 tile, one
// (pixel, batch, angle-half) chain per thread. blockIdx.z in [0,4):
// b = z>>1, half = z&1. 262144 threads -> ~55 warps/SM. One LDG.64 per sample.
// ============================================================================
__global__ __launch_bounds__(256) void bp_kernel() {
    __shared__ float2 s_trig[HALF_A];
    int tid = threadIdx.y * 16 + threadIdx.x;
    int z = blockIdx.z;
    int b = z >> 1;
    int h = z & 1;
    int a0 = h * HALF_A;

    const float C1 = 32761.0f / (127.5f * 1.41421356237309515f);  // 181^2/(127.5*sqrt2)
    for (int a = tid; a < HALF_A; a += 256) {
        float sa, ca;
        sincospif((float)(a0 + a) * (1.0f / 360.0f), &sa, &ca);   // angle = idx*pi/360
        s_trig[a] = make_float2(ca * C1, sa * C1);
    }
    __syncthreads();

    int x = blockIdx.x * 16 + threadIdx.x;
    int y = blockIdx.y * 16 + threadIdx.y;
    float xf = fmaf((float)x, 2.0f / 255.0f, -1.0f);
    float yf = fmaf((float)y, 2.0f / 255.0f, -1.0f);

    const float2* p = g_filt2 + b * BATCH_OFF + a0 * SROW;
    float acc = 0.0f;
    #pragma unroll 4
    for (int a = 0; a < HALF_A; a++) {
        float2 cs = s_trig[a];
        float u  = fmaf(xf, cs.x, fmaf(yf, cs.y, 257.0f));  // 257 = PAD + (D-1)/2
        float uf = floorf(u);
        int   i0 = (int)uf;
        float w1 = u - uf;
        float2 v = __ldg(p + i0);
        acc = fmaf(w1, v.y - v.x, acc + v.x);               // v.x*(1-w1) + v.y*w1
        p += SROW;
    }

    g_part[z][y * IMG + x] = acc;
}

// ============================================================================
// Kernel 3: combine halves + scale. float4-vectorized, one pass over 0.5 MB.
// ============================================================================
__global__ __launch_bounds__(256) void combine_kernel(float* __restrict__ out) {
    int i = blockIdx.x * 256 + threadIdx.x;          // 0..32767 (float4 index)
    int b = i >> 14;                                  // 16384 float4 per batch
    int q = i & 16383;
    const float4* p0 = (const float4*)g_part[b * 2];
    const float4* p1 = (const float4*)g_part[b * 2 + 1];
    float4 u = p0[q];
    float4 v = p1[q];
    const float SC = (float)(M_PI / 360.0);
    float4 w;
    w.x = (u.x + v.x) * SC;
    w.y = (u.y + v.y) * SC;
    w.z = (u.z + v.z) * SC;
    w.w = (u.w + v.w) * SC;
    ((float4*)out)[i] = w;
}

// ============================================================================
extern "C" void kernel_launch(void* const* d_in, const int* in_sizes, int n_in,
                              void* d_out, int out_size) {
    const float* sino = (const float*)d_in[0];   // (2,1,360,363) float32
    float* out = (float*)d_out;                  // (2,1,256,256) float32

    filter_kernel<<<NROWS / 2, 192>>>(sino);
    bp_kernel<<<dim3(IMG / 16, IMG / 16, 4), dim3(16, 16)>>>();
    combine_kernel<<<128, 256>>>(out);
}

// round 13
// speedup vs baseline: 2.4053x; 1.1405x over previous
#include <cuda_runtime.h>
#include <math.h>

#define D_DET   363
#define N_ANG   360
#define HALF_A  180
#define IMG     256
#define PAD     76
#define SROW    544                    // padded row length (float2 pairs)
#define NROWS   720                    // B * N_ANG
#define BATCH_OFF (N_ANG * SROW)       // float2 elements between batch 0 and batch 1

// Delta-packed, zero-padded filtered sinogram: g_filt2[row][i] = (f[i], f[i+1]-f[i])
__device__ float2 g_filt2[NROWS * SROW];
// Partial backprojection sums: [batch*2 + half][pixel]
__device__ float  g_part[4][IMG * IMG];

// ============================================================================
// Kernel 1: ramp-filter via exact circular convolution (== ifft(fft*2|f|).real)
// 1 row per block (grid 720 -> ~29 warps/SM), 2 outputs/thread, float2 LDS:
// one broadcast float2 (sino pair) + one streamed float2 (h pair) per 2 k.
// ============================================================================
__global__ __launch_bounds__(192) void filter_kernel(const float* __restrict__ sino) {
    __shared__ float2 s_h2p[368];      // 736 floats; s_h2[j+4] = h[(j-362) mod 363]
    __shared__ float2 s_row2[184];     // 368 floats; [363..367] = 0
    __shared__ float  s_out[546];      // full padded row (zeros in pads)
    float* s_h2  = (float*)s_h2p;
    float* s_row = (float*)s_row2;

    int t   = threadIdx.x;             // 0..191
    int row = blockIdx.x;              // 0..719

    // ---- build h2 table (proven) ----
    // h[n] = (182 cos(362 n pi/363) - 181 cos(364 n pi/363) - 1) / (363^2 sin^2(n pi/363))
    for (int i = t; i < 736; i += 192) {
        float v = 0.0f;
        int jj = i - 4;
        if (jj >= 0 && jj <= 724) {
            int n = (jj >= 362) ? (jj - 362) : (jj + 1);   // (jj-362) mod 363
            if (n == 0) {
                v = 2.0f * 181.0f * 182.0f / (363.0f * 363.0f);
            } else {
                int r1 = (362 * n) % 726;                  // exact mod-2pi reduction
                int r2 = (364 * n) % 726;
                float c1 = cospif((float)r1 * (1.0f / 363.0f));
                float c2 = cospif((float)r2 * (1.0f / 363.0f));
                float s  = sinpif((float)n  * (1.0f / 363.0f));
                v = (182.0f * c1 - 181.0f * c2 - 1.0f) / (363.0f * 363.0f * s * s);
            }
        }
        s_h2[i] = v;
    }
    for (int i = t; i < 368; i += 192)
        s_row[i] = (i < D_DET) ? sino[row * D_DET + i] : 0.0f;
    for (int i = t; i < 546; i += 192) s_out[i] = 0.0f;
    __syncthreads();

    // ---- convolution: outputs d0, d0+1; h window slides 2 per double-step ----
    if (t < 182) {
        int d0   = 2 * t;                        // 0..362
        int base = 366 + d0;                     // even -> float2-aligned pairs
        float w0 = s_h2[base];
        float w1 = s_h2[base + 1];
        int hb2  = (base - 2) >> 1;              // float2 index of s_h2[base-2]
        float a0 = 0.f, a1 = 0.f;
        #pragma unroll 4
        for (int k2 = 0; k2 < 182; k2++) {       // k = 2*k2, 2*k2+1 (s_row[363]=0)
            float2 sv = s_row2[k2];              // broadcast across warp
            float2 hp = s_h2p[hb2 - k2];         // (h[base-2-2k2], h[base-1-2k2])
            a0 = fmaf(sv.x, w0, a0);
            a1 = fmaf(sv.x, w1, a1);
            a0 = fmaf(sv.y, hp.y, a0);
            a1 = fmaf(sv.y, w0, a1);
            w1 = hp.y; w0 = hp.x;
        }
        s_out[PAD + d0] = a0;
        if (d0 + 1 < D_DET) s_out[PAD + d0 + 1] = a1;
    }
    __syncthreads();

    // ---- write delta-packed padded row: (f[c], f[c+1]-f[c]) ----
    for (int i = t; i < SROW; i += 192) {
        float v0 = s_out[i];
        g_filt2[row * SROW + i] = make_float2(v0, s_out[i + 1] - v0);
    }
}

// ============================================================================
// Kernel 2: backprojection (R9-proven structure). 16x16 tile; one
// (pixel, batch, angle-half) chain per thread; z = batch*2 + half.
// One LDG.64 per sample; delta form saves one FADD per sample.
// ============================================================================
__global__ __launch_bounds__(256) void bp_kernel() {
    __shared__ float2 s_trig[HALF_A];
    int tid = threadIdx.y * 16 + threadIdx.x;
    int z = blockIdx.z;
    int b = z >> 1;
    int h = z & 1;
    int a0 = h * HALF_A;

    const float C1 = 32761.0f / (127.5f * 1.41421356237309515f);  // 181^2/(127.5*sqrt2)
    for (int a = tid; a < HALF_A; a += 256) {
        float sa, ca;
        sincospif((float)(a0 + a) * (1.0f / 360.0f), &sa, &ca);   // angle = idx*pi/360
        s_trig[a] = make_float2(ca * C1, sa * C1);
    }
    __syncthreads();

    int x = blockIdx.x * 16 + threadIdx.x;
    int y = blockIdx.y * 16 + threadIdx.y;
    float xf = fmaf((float)x, 2.0f / 255.0f, -1.0f);
    float yf = fmaf((float)y, 2.0f / 255.0f, -1.0f);

    const float2* p = g_filt2 + b * BATCH_OFF + a0 * SROW;
    float acc = 0.0f;
    #pragma unroll 4
    for (int a = 0; a < HALF_A; a++) {
        float2 cs = s_trig[a];
        float u  = fmaf(xf, cs.x, fmaf(yf, cs.y, 257.0f));  // 257 = PAD + (D-1)/2
        float uf = floorf(u);
        int   i0 = (int)uf;
        float w1 = u - uf;
        float2 v = __ldg(p + i0);
        acc = fmaf(w1, v.y, acc + v.x);                     // f0 + w*(f1-f0)
        p += SROW;
    }

    g_part[z][y * IMG + x] = acc;
}

// ============================================================================
// Kernel 3: combine halves + scale. float4-vectorized, one pass over 0.5 MB.
// ============================================================================
__global__ __launch_bounds__(256) void combine_kernel(float* __restrict__ out) {
    int i = blockIdx.x * 256 + threadIdx.x;          // 0..32767 (float4 index)
    int b = i >> 14;                                  // 16384 float4 per batch
    int q = i & 16383;
    const float4* p0 = (const float4*)g_part[b * 2];
    const float4* p1 = (const float4*)g_part[b * 2 + 1];
    float4 u = p0[q];
    float4 v = p1[q];
    const float SC = (float)(M_PI / 360.0);
    float4 w;
    w.x = (u.x + v.x) * SC;
    w.y = (u.y + v.y) * SC;
    w.z = (u.z + v.z) * SC;
    w.w = (u.w + v.w) * SC;
    ((float4*)out)[i] = w;
}

// ============================================================================
extern "C" void kernel_launch(void* const* d_in, const int* in_sizes, int n_in,
                              void* d_out, int out_size) {
    const float* sino = (const float*)d_in[0];   // (2,1,360,363) float32
    float* out = (float*)d_out;                  // (2,1,256,256) float32

    filter_kernel<<<NROWS, 192>>>(sino);
    bp_kernel<<<dim3(IMG / 16, IMG / 16, 4), dim3(16, 16)>>>();
    combine_kernel<<<128, 256>>>(out);
}

// round 14
// speedup vs baseline: 2.8758x; 1.1956x over previous
#include <cuda_runtime.h>
#include <math.h>

#define D_DET   363
#define N_ANG   360
#define QTR_A   90
#define IMG     256
#define PAD     76
#define SROW    544                    // padded row length (float2 pairs)
#define NROWS   720                    // B * N_ANG
#define BATCH_OFF (N_ANG * SROW)       // float2 elements between batch 0 and batch 1

// Delta-packed, zero-padded filtered sinogram: g_filt2[row][i] = (f[i], f[i+1]-f[i])
__device__ float2 g_filt2[NROWS * SROW];
// Ramp impulse-response table: g_h2[j+4] = h[(j-362) mod 363], zeros at edges
__device__ float  g_h2[736];
// Partial backprojection sums: [batch*4 + quarter][pixel]
__device__ float  g_part[8][IMG * IMG];

// ============================================================================
// Kernel 0: prep — compute the 736-entry h table ONCE (was rebuilt per filter
// block: ~1.6M MUFU ops chip-wide). 768 threads across 6 blocks.
// h[n] = (182 cos(362 n pi/363) - 181 cos(364 n pi/363) - 1) / (363^2 sin^2(n pi/363))
// ============================================================================
__global__ __launch_bounds__(128) void prep_kernel() {
    int i = blockIdx.x * 128 + threadIdx.x;
    if (i >= 736) return;
    float v = 0.0f;
    int jj = i - 4;
    if (jj >= 0 && jj <= 724) {
        int n = (jj >= 362) ? (jj - 362) : (jj + 1);   // (jj-362) mod 363
        if (n == 0) {
            v = 2.0f * 181.0f * 182.0f / (363.0f * 363.0f);
        } else {
            int r1 = (362 * n) % 726;                  // exact mod-2pi reduction
            int r2 = (364 * n) % 726;
            float c1 = cospif((float)r1 * (1.0f / 363.0f));
            float c2 = cospif((float)r2 * (1.0f / 363.0f));
            float s  = sinpif((float)n  * (1.0f / 363.0f));
            v = (182.0f * c1 - 181.0f * c2 - 1.0f) / (363.0f * 363.0f * s * s);
        }
    }
    g_h2[i] = v;
}

// ============================================================================
// Kernel 1: ramp-filter via exact circular convolution (== ifft(fft*2|f|).real)
// 1 row/block, 2 outputs/thread, float2 LDS (R13-proven conv core).
// h table now loaded from global (float4) instead of recomputed.
// ============================================================================
__global__ __launch_bounds__(192) void filter_kernel(const float* __restrict__ sino) {
    __shared__ float2 s_h2p[368];      // 736 floats
    __shared__ float2 s_row2[184];     // 368 floats; [363..367] = 0
    __shared__ float  s_out[546];      // full padded row (zeros in pads)
    float* s_h2  = (float*)s_h2p;
    float* s_row = (float*)s_row2;

    int t   = threadIdx.x;             // 0..191
    int row = blockIdx.x;              // 0..719

    if (t < 184)
        ((float4*)s_h2)[t] = ((const float4*)g_h2)[t];
    for (int i = t; i < 368; i += 192)
        s_row[i] = (i < D_DET) ? __ldg(sino + row * D_DET + i) : 0.0f;
    for (int i = t; i < 546; i += 192) s_out[i] = 0.0f;
    __syncthreads();

    // ---- convolution: outputs d0, d0+1; h window slides 2 per double-step ----
    if (t < 182) {
        int d0   = 2 * t;                        // 0..362
        int base = 366 + d0;                     // even -> float2-aligned pairs
        float w0 = s_h2[base];
        float w1 = s_h2[base + 1];
        int hb2  = (base - 2) >> 1;              // float2 index of s_h2[base-2]
        float a0 = 0.f, a1 = 0.f;
        #pragma unroll 4
        for (int k2 = 0; k2 < 182; k2++) {       // k = 2*k2, 2*k2+1 (s_row[363]=0)
            float2 sv = s_row2[k2];              // broadcast across warp
            float2 hp = s_h2p[hb2 - k2];         // (h[base-2-2k2], h[base-1-2k2])
            a0 = fmaf(sv.x, w0, a0);
            a1 = fmaf(sv.x, w1, a1);
            a0 = fmaf(sv.y, hp.y, a0);
            a1 = fmaf(sv.y, w0, a1);
            w1 = hp.y; w0 = hp.x;
        }
        s_out[PAD + d0] = a0;
        if (d0 + 1 < D_DET) s_out[PAD + d0 + 1] = a1;
    }
    __syncthreads();

    // ---- write delta-packed padded row: (f[c], f[c+1]-f[c]) ----
    for (int i = t; i < SROW; i += 192) {
        float v0 = s_out[i];
        g_filt2[row * SROW + i] = make_float2(v0, s_out[i + 1] - v0);
    }
}

// ============================================================================
// Kernel 2: backprojection. 16x16 tile; z = angle quarter (90 angles/chain);
// each thread handles BOTH batches (shared u/floor/address; 2nd LDG via
// compile-time immediate offset). 8192 warps -> ~55 warps/SM.
// ============================================================================
__global__ __launch_bounds__(256) void bp_kernel() {
    __shared__ float2 s_trig[QTR_A];
    int tid = threadIdx.y * 16 + threadIdx.x;
    int q = blockIdx.z;                // angle quarter
    int a0 = q * QTR_A;

    const float C1 = 32761.0f / (127.5f * 1.41421356237309515f);  // 181^2/(127.5*sqrt2)
    if (tid < QTR_A) {
        float sa, ca;
        sincospif((float)(a0 + tid) * (1.0f / 360.0f), &sa, &ca); // angle = idx*pi/360
        s_trig[tid] = make_float2(ca * C1, sa * C1);
    }
    __syncthreads();

    int x = blockIdx.x * 16 + threadIdx.x;
    int y = blockIdx.y * 16 + threadIdx.y;
    float xf = fmaf((float)x, 2.0f / 255.0f, -1.0f);
    float yf = fmaf((float)y, 2.0f / 255.0f, -1.0f);

    const float2* p = g_filt2 + a0 * SROW;
    float accA = 0.0f, accB = 0.0f;
    #pragma unroll 5
    for (int a = 0; a < QTR_A; a++) {
        float2 cs = s_trig[a];
        float u  = fmaf(xf, cs.x, fmaf(yf, cs.y, 257.0f));  // 257 = PAD + (D-1)/2
        int   i0 = __float2int_rd(u);                       // u > 0: exact floor
        float w  = u - (float)i0;
        float2 vA = __ldg(p + i0);
        float2 vB = __ldg(p + i0 + BATCH_OFF);              // +1.53MB immediate
        accA = fmaf(w, vA.y, accA + vA.x);                  // f0 + w*(f1-f0)
        accB = fmaf(w, vB.y, accB + vB.x);
        p += SROW;
    }

    g_part[q][y * IMG + x]     = accA;
    g_part[4 + q][y * IMG + x] = accB;
}

// ============================================================================
// Kernel 3: combine quarters + scale. float4-vectorized.
// ============================================================================
__global__ __launch_bounds__(256) void combine_kernel(float* __restrict__ out) {
    int i = blockIdx.x * 256 + threadIdx.x;          // 0..32767 (float4 index)
    int b = i >> 14;                                  // 16384 float4 per batch
    int p = i & 16383;
    const float4* g0 = (const float4*)g_part[b * 4 + 0];
    const float4* g1 = (const float4*)g_part[b * 4 + 1];
    const float4* g2 = (const float4*)g_part[b * 4 + 2];
    const float4* g3 = (const float4*)g_part[b * 4 + 3];
    float4 u0 = g0[p], u1 = g1[p], u2 = g2[p], u3 = g3[p];
    const float SC = (float)(M_PI / 360.0);
    float4 w;
    w.x = ((u0.x + u1.x) + (u2.x + u3.x)) * SC;
    w.y = ((u0.y + u1.y) + (u2.y + u3.y)) * SC;
    w.z = ((u0.z + u1.z) + (u2.z + u3.z)) * SC;
    w.w = ((u0.w + u1.w) + (u2.w + u3.w)) * SC;
    ((float4*)out)[i] = w;
}

// ============================================================================
extern "C" void kernel_launch(void* const* d_in, const int* in_sizes, int n_in,
                              void* d_out, int out_size) {
    const float* sino = (const float*)d_in[0];   // (2,1,360,363) float32
    float* out = (float*)d_out;                  // (2,1,256,256) float32

    prep_kernel<<<6, 128>>>();
    filter_kernel<<<NROWS, 192>>>(sino);
    bp_kernel<<<dim3(IMG / 16, IMG / 16, 4), dim3(16, 16)>>>();
    combine_kernel<<<128, 256>>>(out);
}